// round 7
// baseline (speedup 1.0000x reference)
#include <cuda_runtime.h>
#include <math.h>

#define NN 16384
#define DD 64
#define KK 3
#define G 16
#define CELLS (G * G * G)   // 4096
#define CAP 48              // bucket capacity (P(overflow) ~ 1e-40 for Poisson(4))

#define TX 4
#define TY 4
#define TZ 2
#define LX (TX + 2)
#define LY (TY + 2)
#define LZ (TZ + 2)
#define LCELLS (LX * LY * LZ)   // 144
#define TCELLS (TX * TY * TZ)   // 32
#define MAXPTS 2048

// ---------------- scratch (device globals, no allocation) ----------------
__device__ float g_x[NN * DD];      // features after LN2
__device__ float g_xnorm[NN];       // row L2 norms
__device__ int   g_knn[NN * KK];
__device__ float g_ew[NN * KK];
__device__ float g_dis[NN];         // rsqrt(deg)
__device__ float g_t[NN * DD];      // relu(LN(gcn1 out))

__device__ int    g_cnt[CELLS];
__device__ float4 g_bkt[CELLS * CAP];   // (x, y, z, idx-as-bits)

__device__ __forceinline__ float wsum(float v) {
    #pragma unroll
    for (int o = 16; o > 0; o >>= 1) v += __shfl_xor_sync(0xFFFFFFFFu, v, o);
    return v;
}

__device__ __forceinline__ int cell_of(float x, float y, float z) {
    int cx = min(G - 1, max(0, (int)(x * (float)G)));
    int cy = min(G - 1, max(0, (int)(y * (float)G)));
    int cz = min(G - 1, max(0, (int)(z * (float)G)));
    return (cz * G + cy) * G + cx;
}

// exact reference arithmetic helpers
__device__ __forceinline__ float sq_exact(float x, float y, float z) {
    return __fadd_rn(__fadd_rn(__fmul_rn(x, x), __fmul_rn(y, y)), __fmul_rn(z, z));
}
__device__ __forceinline__ float dist_exact(float qx, float qy, float qz, float qsq,
                                            float px, float py, float pz, float psq) {
    float dot = __fmaf_rn(qz, pz, __fmaf_rn(qy, py, __fmul_rn(qx, px)));
    return __fmaf_rn(-2.0f, dot, __fadd_rn(qsq, psq));
}

__device__ __forceinline__ bool knn_lt(float d, int i, float D, int I) {
    return d < D || (d == D && i < I);
}

__device__ __forceinline__ void insert3(float d, int j,
                                        float& d0, float& d1, float& d2,
                                        int& i0, int& i1, int& i2) {
    if (knn_lt(d, j, d2, i2)) {
        if (knn_lt(d, j, d1, i1)) {
            if (knn_lt(d, j, d0, i0)) { d2 = d1; i2 = i1; d1 = d0; i1 = i0; d0 = d; i0 = j; }
            else                      { d2 = d1; i2 = i1; d1 = d;  i1 = j; }
        } else                        { d2 = d;  i2 = j; }
    }
}

// serial global ring walk (slow path: stop-bound failures / smem overflow; rare)
__device__ void ring_walk(int q, float qx, float qy, float qz, float qsq,
                          int cx, int cy, int cz, int rstart,
                          float& d0, float& d1, float& d2,
                          int& i0, int& i1, int& i2) {
    const float h = 1.0f / (float)G;
    for (int r = rstart; ; r++) {
        int z0 = max(cz - r, 0), z1 = min(cz + r, G - 1);
        int y0 = max(cy - r, 0), y1 = min(cy + r, G - 1);
        int x0 = max(cx - r, 0), x1 = min(cx + r, G - 1);
        for (int zz = z0; zz <= z1; zz++)
            for (int yy = y0; yy <= y1; yy++)
                for (int xx = x0; xx <= x1; xx++) {
                    int ma = max(abs(xx - cx), max(abs(yy - cy), abs(zz - cz)));
                    if (ma != r) continue;
                    int c = (zz * G + yy) * G + xx;
                    int cnt = min(g_cnt[c], CAP);
                    const float4* bp = &g_bkt[c * CAP];
                    for (int t = 0; t < cnt; t++) {
                        float4 p = bp[t];
                        int j = __float_as_int(p.w);
                        if (j == q) continue;
                        float d = dist_exact(qx, qy, qz, qsq, p.x, p.y, p.z,
                                             sq_exact(p.x, p.y, p.z));
                        insert3(d, j, d0, d1, d2, i0, i1, i2);
                    }
                }
        bool full = (x0 == 0 && x1 == G - 1 && y0 == 0 && y1 == G - 1 &&
                     z0 == 0 && z1 == G - 1);
        if (full) return;
        if (i2 != 0x7fffffff) {
            float m = INFINITY;
            if (cx - r > 0)     m = fminf(m, qx - (float)(cx - r) * h);
            if (cx + r < G - 1) m = fminf(m, (float)(cx + r + 1) * h - qx);
            if (cy - r > 0)     m = fminf(m, qy - (float)(cy - r) * h);
            if (cy + r < G - 1) m = fminf(m, (float)(cy + r + 1) * h - qy);
            if (cz - r > 0)     m = fminf(m, qz - (float)(cz - r) * h);
            if (cz + r < G - 1) m = fminf(m, (float)(cz + r + 1) * h - qz);
            if (m * m > d2 + 1e-5f) return;   // conservative: rounding skew <= ~3e-6
        }
    }
}

// ---------------- grid zero ----------------
__global__ void grid_zero() {
    g_cnt[blockIdx.x * 256 + threadIdx.x] = 0;
}

// ---------------- merged: grid_build (blocks 0..63) + LN chain (blocks 64..) ----------------
__global__ void build_ln(const float* __restrict__ coords,
                         const float* __restrict__ in,
                         const float* __restrict__ g1, const float* __restrict__ b1,
                         const float* __restrict__ g2, const float* __restrict__ b2) {
    if (blockIdx.x < NN / 256) {
        int i = blockIdx.x * 256 + threadIdx.x;
        float x = coords[3 * i], y = coords[3 * i + 1], z = coords[3 * i + 2];
        int c = cell_of(x, y, z);
        int pos = atomicAdd(&g_cnt[c], 1);
        if (pos < CAP) g_bkt[c * CAP + pos] = make_float4(x, y, z, __int_as_float(i));
        return;
    }
    int bb = blockIdx.x - NN / 256;
    int lane = threadIdx.x & 31;
    int ty = threadIdx.x >> 5;
    int i = bb * 8 + ty;
    const float* row = in + (size_t)i * DD;
    float a0 = row[lane], a1 = row[lane + 32];

    float m = wsum(a0 + a1) * (1.0f / 64.0f);
    float d0 = a0 - m, d1 = a1 - m;
    float v = wsum(d0 * d0 + d1 * d1) * (1.0f / 64.0f);
    float inv = rsqrtf(v + 1e-5f);
    float y0 = d0 * inv * g1[lane] + b1[lane];
    float y1 = d1 * inv * g1[lane + 32] + b1[lane + 32];

    y0 *= 2.0f; y1 *= 2.0f;   // x = x + x

    m = wsum(y0 + y1) * (1.0f / 64.0f);
    d0 = y0 - m; d1 = y1 - m;
    v = wsum(d0 * d0 + d1 * d1) * (1.0f / 64.0f);
    inv = rsqrtf(v + 1e-5f);
    float x0 = d0 * inv * g2[lane] + b2[lane];
    float x1 = d1 * inv * g2[lane + 32] + b2[lane + 32];

    g_x[(size_t)i * DD + lane] = x0;
    g_x[(size_t)i * DD + lane + 32] = x1;

    float s = wsum(x0 * x0 + x1 * x1);
    if (lane == 0) g_xnorm[i] = fmaxf(sqrtf(s), 1e-8f);
}

// ---------------- K2: tiled KNN, thread per query, halo in smem ----------------
__global__ void knn_tile() {
    __shared__ int s_cnt[LCELLS], s_off[LCELLS + 1], s_gcell[LCELLS];
    __shared__ int s_q[TCELLS + 1], s_qcell[TCELLS];
    __shared__ float4 s_pts[MAXPTS];
    __shared__ int s_ovf;

    int tid = threadIdx.x;
    int b = blockIdx.x;
    int bx = b & 3, by = (b >> 2) & 3, bz = b >> 4;
    int hx0 = bx * TX - 1, hy0 = by * TY - 1, hz0 = bz * TZ - 1;

    // counts + global cell ids for the 6x6x4 halo
    for (int c = tid; c < LCELLS; c += 128) {
        int lz = c / (LX * LY), rem = c % (LX * LY), ly = rem / LX, lx = rem % LX;
        int gx = hx0 + lx, gy = hy0 + ly, gz = hz0 + lz;
        int cnt = 0, gc = -1;
        if (gx >= 0 && gx < G && gy >= 0 && gy < G && gz >= 0 && gz < G) {
            gc = (gz * G + gy) * G + gx;
            cnt = min(g_cnt[gc], CAP);
        }
        s_cnt[c] = cnt;
        s_gcell[c] = gc;
    }
    __syncthreads();
    if (tid == 0) {
        int acc = 0;
        for (int c = 0; c < LCELLS; c++) { s_off[c] = acc; acc += s_cnt[c]; }
        s_off[LCELLS] = acc;
        s_ovf = (acc > MAXPTS);
        int qa = 0;
        for (int i = 0; i < TCELLS; i++) {
            int tlx = 1 + (i & 3), tly = 1 + ((i >> 2) & 3), tlz = 1 + (i >> 4);
            int ct = (tlz * LY + tly) * LX + tlx;
            s_qcell[i] = ct;
            s_q[i] = qa;
            qa += s_cnt[ct];
        }
        s_q[TCELLS] = qa;
    }
    __syncthreads();
    bool ovf = s_ovf != 0;
    if (!ovf) {
        for (int c = tid; c < LCELLS; c += 128) {
            int cnt = s_cnt[c], dst = s_off[c], gc = s_gcell[c];
            for (int t = 0; t < cnt; t++) s_pts[dst + t] = g_bkt[gc * CAP + t];
        }
    }
    __syncthreads();

    int qtotal = s_q[TCELLS];
    const float h = 1.0f / (float)G;
    for (int t = tid; t < qtotal; t += 128) {
        int ti = 0;
        while (s_q[ti + 1] <= t) ti++;
        int ct = s_qcell[ti];
        int slot = t - s_q[ti];
        float4 qp = ovf ? g_bkt[s_gcell[ct] * CAP + slot] : s_pts[s_off[ct] + slot];
        float qx = qp.x, qy = qp.y, qz = qp.z;
        int q = __float_as_int(qp.w);
        float qsq = sq_exact(qx, qy, qz);
        int lz = ct / (LX * LY), rem = ct % (LX * LY), ly = rem / LX, lx = rem % LX;
        int cx = hx0 + lx, cy = hy0 + ly, cz = hz0 + lz;

        float d0 = INFINITY, d1 = INFINITY, d2 = INFINITY;
        int i0 = 0x7fffffff, i1 = 0x7fffffff, i2 = 0x7fffffff;

        if (!ovf) {
            // 27-cell neighborhood from smem (exactly the ring<=1 cell set)
            #pragma unroll
            for (int dz = -1; dz <= 1; dz++)
                #pragma unroll
                for (int dy = -1; dy <= 1; dy++)
                    #pragma unroll
                    for (int dx = -1; dx <= 1; dx++) {
                        int cc = ct + (dz * LY + dy) * LX + dx;
                        int off = s_off[cc], cnt = s_cnt[cc];
                        for (int s = 0; s < cnt; s++) {
                            float4 p = s_pts[off + s];
                            int j = __float_as_int(p.w);
                            if (j == q) continue;
                            float d = dist_exact(qx, qy, qz, qsq, p.x, p.y, p.z,
                                                 sq_exact(p.x, p.y, p.z));
                            insert3(d, j, d0, d1, d2, i0, i1, i2);
                        }
                    }
            // conservative stopping bound at r = 1
            float m = INFINITY;
            if (cx - 1 > 0)     m = fminf(m, qx - (float)(cx - 1) * h);
            if (cx + 1 < G - 1) m = fminf(m, (float)(cx + 2) * h - qx);
            if (cy - 1 > 0)     m = fminf(m, qy - (float)(cy - 1) * h);
            if (cy + 1 < G - 1) m = fminf(m, (float)(cy + 2) * h - qy);
            if (cz - 1 > 0)     m = fminf(m, qz - (float)(cz - 1) * h);
            if (cz + 1 < G - 1) m = fminf(m, (float)(cz + 2) * h - qz);
            bool ok = (i2 != 0x7fffffff) && (m * m > d2 + 1e-5f);
            if (!ok)
                ring_walk(q, qx, qy, qz, qsq, cx, cy, cz, 2, d0, d1, d2, i0, i1, i2);
        } else {
            // smem overflow (practically impossible): all-global path
            int c = (cz * G + cy) * G + cx;
            int cnt = min(g_cnt[c], CAP);
            const float4* bp = &g_bkt[c * CAP];
            for (int s = 0; s < cnt; s++) {
                float4 p = bp[s];
                int j = __float_as_int(p.w);
                if (j == q) continue;
                float d = dist_exact(qx, qy, qz, qsq, p.x, p.y, p.z,
                                     sq_exact(p.x, p.y, p.z));
                insert3(d, j, d0, d1, d2, i0, i1, i2);
            }
            ring_walk(q, qx, qy, qz, qsq, cx, cy, cz, 1, d0, d1, d2, i0, i1, i2);
        }

        g_knn[q * 3 + 0] = i0;
        g_knn[q * 3 + 1] = i1;
        g_knn[q * 3 + 2] = i2;
    }
}

// ---------------- K3: edge weights ----------------
__global__ void ew_kernel() {
    int i = blockIdx.x * 8 + threadIdx.y;
    int lane = threadIdx.x;
    float xi0 = g_x[(size_t)i * DD + lane];
    float xi1 = g_x[(size_t)i * DD + lane + 32];
    float ni = g_xnorm[i];

    float deg = 1.0f;
    float ews[KK];
    #pragma unroll
    for (int k = 0; k < KK; k++) {
        int nb = g_knn[i * 3 + k];
        float dot = wsum(xi0 * g_x[(size_t)nb * DD + lane] +
                         xi1 * g_x[(size_t)nb * DD + lane + 32]);
        float z = dot / (g_xnorm[nb] * ni);
        float e = 1.0f / (1.0f + expf(-z));
        ews[k] = e;
        deg += e;
    }
    float dis = rsqrtf(deg);
    if (lane == 0) {
        #pragma unroll
        for (int k = 0; k < KK; k++) g_ew[i * 3 + k] = ews[k];
        g_dis[i] = dis;
    }
}

// ---------------- K4/K5: fused GCN (32 rows/block, col-pair per thread) ----------------
template <int EPI>
__global__ void gcn_kernel(const float* __restrict__ W, const float* __restrict__ b,
                           const float* __restrict__ lng, const float* __restrict__ lnb,
                           float* __restrict__ out) {
    __shared__ float sW[DD * DD];
    __shared__ float sZ[8][DD];
    int tid = threadIdx.y * 32 + threadIdx.x;
    for (int k = tid; k < DD * DD; k += 256) sW[k] = W[k];
    __syncthreads();

    int lane = threadIdx.x;
    int ty = threadIdx.y;
    int c0 = 2 * lane;
    const float* xin = (EPI == 1) ? g_x : g_t;
    float2 bb = *(const float2*)&b[c0];

    #pragma unroll
    for (int rb = 0; rb < 4; rb++) {
        int i = blockIdx.x * 32 + rb * 8 + ty;

        float dii = g_dis[i];
        float cs = dii * dii;
        float2 xi = *(const float2*)&xin[(size_t)i * DD + c0];
        float z0 = cs * xi.x, z1 = cs * xi.y;
        #pragma unroll
        for (int k = 0; k < KK; k++) {
            int nb = g_knn[i * 3 + k];
            float c = g_dis[nb] * g_ew[i * 3 + k] * dii;
            float2 xn = *(const float2*)&xin[(size_t)nb * DD + c0];
            z0 = fmaf(c, xn.x, z0);
            z1 = fmaf(c, xn.y, z1);
        }
        sZ[ty][c0] = z0;
        sZ[ty][c0 + 1] = z1;
        __syncwarp();

        float acc0 = 0.0f, acc1 = 0.0f;
        #pragma unroll
        for (int k = 0; k < DD; k++) {
            float zk = sZ[ty][k];
            float2 w = *(const float2*)&sW[k * DD + c0];
            acc0 = fmaf(zk, w.x, acc0);
            acc1 = fmaf(zk, w.y, acc1);
        }
        acc0 += bb.x;
        acc1 += bb.y;

        if (EPI == 1) {
            float m = wsum(acc0 + acc1) * (1.0f / 64.0f);
            float e0 = acc0 - m, e1 = acc1 - m;
            float v = wsum(e0 * e0 + e1 * e1) * (1.0f / 64.0f);
            float inv = rsqrtf(v + 1e-5f);
            float2 o;
            o.x = fmaxf(e0 * inv * lng[c0] + lnb[c0], 0.0f);
            o.y = fmaxf(e1 * inv * lng[c0 + 1] + lnb[c0 + 1], 0.0f);
            *(float2*)&g_t[(size_t)i * DD + c0] = o;
        } else {
            float2 xv = *(const float2*)&g_x[(size_t)i * DD + c0];
            float2 o;
            o.x = fmaf(2.0f, xv.x, acc0);
            o.y = fmaf(2.0f, xv.y, acc1);
            *(float2*)&out[(size_t)i * DD + c0] = o;
        }
        __syncwarp();
    }
}

// ---------------- launch ----------------
extern "C" void kernel_launch(void* const* d_in, const int* in_sizes, int n_in,
                              void* d_out, int out_size) {
    const float* feat   = (const float*)d_in[0];
    const float* coords = (const float*)d_in[4];
    const float* n1g = (const float*)d_in[5];
    const float* n1b = (const float*)d_in[6];
    const float* n2g = (const float*)d_in[7];
    const float* n2b = (const float*)d_in[8];
    const float* gng = (const float*)d_in[9];
    const float* gnb = (const float*)d_in[10];
    const float* W1  = (const float*)d_in[11];
    const float* b1  = (const float*)d_in[12];
    const float* W2  = (const float*)d_in[13];
    const float* b2  = (const float*)d_in[14];
    float* out = (float*)d_out;

    dim3 th(32, 8);
    grid_zero<<<CELLS / 256, 256>>>();
    build_ln<<<NN / 256 + NN / 8, 256>>>(coords, feat, n1g, n1b, n2g, n2b);
    knn_tile<<<128, 128>>>();
    ew_kernel<<<NN / 8, th>>>();
    gcn_kernel<1><<<NN / 32, th>>>(W1, b1, gng, gnb, nullptr);
    gcn_kernel<2><<<NN / 32, th>>>(W2, b2, nullptr, nullptr, out);
}

// round 8
// speedup vs baseline: 1.4390x; 1.4390x over previous
#include <cuda_runtime.h>
#include <math.h>

#define NN 16384
#define DD 64
#define KK 3
#define G 16
#define CELLS (G * G * G)   // 4096
#define CAP 48              // bucket capacity (P(overflow) ~ 1e-40 for Poisson(4))

// ---------------- scratch (device globals, no allocation) ----------------
__device__ float g_x[NN * DD];      // features after LN2
__device__ float g_xnorm[NN];       // row L2 norms
__device__ int   g_knn[NN * KK];
__device__ float g_ew[NN * KK];
__device__ float g_dis[NN];         // rsqrt(deg)
__device__ float g_t[NN * DD];      // relu(LN(gcn1 out))

__device__ int    g_cnt[CELLS];
__device__ float4 g_bkt[CELLS * CAP];   // (x, y, z, idx-as-bits)

__device__ __forceinline__ float wsum(float v) {
    #pragma unroll
    for (int o = 16; o > 0; o >>= 1) v += __shfl_xor_sync(0xFFFFFFFFu, v, o);
    return v;
}

__device__ __forceinline__ int cell_of(float x, float y, float z) {
    int cx = min(G - 1, max(0, (int)(x * (float)G)));
    int cy = min(G - 1, max(0, (int)(y * (float)G)));
    int cz = min(G - 1, max(0, (int)(z * (float)G)));
    return (cz * G + cy) * G + cx;
}

// ---------------- grid zero ----------------
__global__ void grid_zero() {
    g_cnt[blockIdx.x * 256 + threadIdx.x] = 0;
}

// ---------------- merged: grid_build (blocks 0..63) + LN chain ----------------
__global__ void build_ln(const float* __restrict__ coords,
                         const float* __restrict__ in,
                         const float* __restrict__ g1, const float* __restrict__ b1,
                         const float* __restrict__ g2, const float* __restrict__ b2) {
    if (blockIdx.x < NN / 256) {
        int i = blockIdx.x * 256 + threadIdx.x;
        float x = coords[3 * i], y = coords[3 * i + 1], z = coords[3 * i + 2];
        int c = cell_of(x, y, z);
        int pos = atomicAdd(&g_cnt[c], 1);
        if (pos < CAP) g_bkt[c * CAP + pos] = make_float4(x, y, z, __int_as_float(i));
        return;
    }
    int bb = blockIdx.x - NN / 256;
    int lane = threadIdx.x & 31;
    int ty = threadIdx.x >> 5;
    int i = bb * 8 + ty;
    const float* row = in + (size_t)i * DD;
    float a0 = row[lane], a1 = row[lane + 32];

    float m = wsum(a0 + a1) * (1.0f / 64.0f);
    float d0 = a0 - m, d1 = a1 - m;
    float v = wsum(d0 * d0 + d1 * d1) * (1.0f / 64.0f);
    float inv = rsqrtf(v + 1e-5f);
    float y0 = d0 * inv * g1[lane] + b1[lane];
    float y1 = d1 * inv * g1[lane + 32] + b1[lane + 32];

    y0 *= 2.0f; y1 *= 2.0f;   // x = x + x

    m = wsum(y0 + y1) * (1.0f / 64.0f);
    d0 = y0 - m; d1 = y1 - m;
    v = wsum(d0 * d0 + d1 * d1) * (1.0f / 64.0f);
    inv = rsqrtf(v + 1e-5f);
    float x0 = d0 * inv * g2[lane] + b2[lane];
    float x1 = d1 * inv * g2[lane + 32] + b2[lane + 32];

    g_x[(size_t)i * DD + lane] = x0;
    g_x[(size_t)i * DD + lane + 32] = x1;

    float s = wsum(x0 * x0 + x1 * x1);
    if (lane == 0) g_xnorm[i] = fmaxf(sqrtf(s), 1e-8f);
}

// ---------------- K2: grid KNN, 8 LANES PER QUERY (4 queries/warp) ----------------
// Each cell of the search region is handled by exactly one lane of the query's
// 8-lane group (ring 1: lane takes cells sub, sub+8, sub+16, sub+24 of the 27).
// Per-lane lists stay disjoint across the whole search. Group merges operate on
// COPIES only. Distance arithmetic mirrors the reference bit-exactly.
__device__ __forceinline__ bool knn_lt(float d, int i, float D, int I) {
    return d < D || (d == D && i < I);
}

__global__ void knn_grid(const float* __restrict__ coords) {
    int lane = threadIdx.x & 31;
    int sub = lane & 7;                       // lane within 8-lane group
    int q = (blockIdx.x * blockDim.x + threadIdx.x) >> 3;   // one query per group

    float qx = coords[3 * q], qy = coords[3 * q + 1], qz = coords[3 * q + 2];
    float qsq = __fadd_rn(__fadd_rn(__fmul_rn(qx, qx), __fmul_rn(qy, qy)),
                          __fmul_rn(qz, qz));
    int cx = min(G - 1, max(0, (int)(qx * (float)G)));
    int cy = min(G - 1, max(0, (int)(qy * (float)G)));
    int cz = min(G - 1, max(0, (int)(qz * (float)G)));
    const float h = 1.0f / (float)G;

    // per-lane disjoint lists
    float d0 = INFINITY, d1 = INFINITY, d2 = INFINITY;
    int i0 = 0x7fffffff, i1 = 0x7fffffff, i2 = 0x7fffffff;

    auto eval_cell_all = [&](int c) {   // this lane evaluates ALL points of cell c
        int cnt = min(g_cnt[c], CAP);
        const float4* bp = &g_bkt[c * CAP];
        for (int t = 0; t < cnt; t++) {
            float4 p = bp[t];
            int j = __float_as_int(p.w);
            if (j == q) continue;
            float psq = __fadd_rn(__fadd_rn(__fmul_rn(p.x, p.x), __fmul_rn(p.y, p.y)),
                                  __fmul_rn(p.z, p.z));
            float dot = __fmaf_rn(qz, p.z, __fmaf_rn(qy, p.y, __fmul_rn(qx, p.x)));
            float d = __fmaf_rn(-2.0f, dot, __fadd_rn(qsq, psq));
            if (knn_lt(d, j, d2, i2)) {
                if (knn_lt(d, j, d1, i1)) {
                    if (knn_lt(d, j, d0, i0)) { d2 = d1; i2 = i1; d1 = d0; i1 = i0; d0 = d; i0 = j; }
                    else                      { d2 = d1; i2 = i1; d1 = d;  i1 = j; }
                } else                        { d2 = d;  i2 = j; }
            }
        }
    };

    // merged copies within the 8-lane group (recomputed at each ring boundary)
    float m0, m1, m2; int n0, n1, n2;
    auto merge_copies = [&]() {
        m0 = d0; m1 = d1; m2 = d2; n0 = i0; n1 = i1; n2 = i2;
        #pragma unroll
        for (int off = 4; off >= 1; off >>= 1) {
            float e0 = __shfl_xor_sync(0xFFFFFFFFu, m0, off);
            float e1 = __shfl_xor_sync(0xFFFFFFFFu, m1, off);
            float e2 = __shfl_xor_sync(0xFFFFFFFFu, m2, off);
            int   j0 = __shfl_xor_sync(0xFFFFFFFFu, n0, off);
            int   j1 = __shfl_xor_sync(0xFFFFFFFFu, n1, off);
            int   j2 = __shfl_xor_sync(0xFFFFFFFFu, n2, off);
            float ee[3] = {e0, e1, e2};
            int   jj[3] = {j0, j1, j2};
            #pragma unroll
            for (int r = 0; r < 3; r++) {
                float d = ee[r]; int i = jj[r];
                if (knn_lt(d, i, m2, n2)) {
                    if (knn_lt(d, i, m1, n1)) {
                        if (knn_lt(d, i, m0, n0)) { m2 = m1; n2 = n1; m1 = m0; n1 = n0; m0 = d; n0 = i; }
                        else                      { m2 = m1; n2 = n1; m1 = d;  n1 = i; }
                    } else                        { m2 = d;  n2 = i; }
                }
            }
        }
    };

    auto stop_ok = [&](int r) -> bool {   // conservative geometric stopping bound
        if (n2 == 0x7fffffff) return false;
        float m = INFINITY;
        if (cx - r > 0)     m = fminf(m, qx - (float)(cx - r) * h);
        if (cx + r < G - 1) m = fminf(m, (float)(cx + r + 1) * h - qx);
        if (cy - r > 0)     m = fminf(m, qy - (float)(cy - r) * h);
        if (cy + r < G - 1) m = fminf(m, (float)(cy + r + 1) * h - qy);
        if (cz - r > 0)     m = fminf(m, qz - (float)(cz - r) * h);
        if (cz + r < G - 1) m = fminf(m, (float)(cz + r + 1) * h - qz);
        return m * m > m2 + 1e-5f;        // rounding skew <= ~3e-6
    };

    // ---- ring 1: 27 cells, lane takes t = sub, sub+8, sub+16, sub+24 ----
    #pragma unroll
    for (int t = sub; t < 27; t += 8) {
        int dz = t / 9 - 1;
        int dy = (t % 9) / 3 - 1;
        int dx = t % 3 - 1;
        int xx = cx + dx, yy = cy + dy, zz = cz + dz;
        if (xx >= 0 && xx < G && yy >= 0 && yy < G && zz >= 0 && zz < G)
            eval_cell_all((zz * G + yy) * G + xx);
    }
    merge_copies();

    bool done;
    {
        bool full = (cx - 1 <= 0 && cx + 1 >= G - 1 && cy - 1 <= 0 && cy + 1 >= G - 1 &&
                     cz - 1 <= 0 && cz + 1 >= G - 1);
        done = full || stop_ok(1);
    }

    // ---- rings r >= 2 (rare): lanes of group stride shell cells by 8 ----
    // warp-uniform loop so the butterfly shuffles stay full-warp
    int r = 2;
    while (__any_sync(0xFFFFFFFFu, !done)) {
        if (!done) {
            int side = 2 * r + 1;
            int ncell = side * side * side;
            for (int t = sub; t < ncell; t += 8) {
                int dz = t / (side * side) - r;
                int rem = t % (side * side);
                int dy = rem / side - r;
                int dx = rem % side - r;
                int ma = max(abs(dx), max(abs(dy), abs(dz)));
                if (ma < r) continue;                      // interior already scanned
                int xx = cx + dx, yy = cy + dy, zz = cz + dz;
                if (xx < 0 || xx >= G || yy < 0 || yy >= G || zz < 0 || zz >= G) continue;
                eval_cell_all((zz * G + yy) * G + xx);
            }
        }
        merge_copies();
        if (!done) {
            bool full = (cx - r <= 0 && cx + r >= G - 1 && cy - r <= 0 && cy + r >= G - 1 &&
                         cz - r <= 0 && cz + r >= G - 1);
            done = full || stop_ok(r);
        }
        r++;
    }

    if (sub == 0) {
        g_knn[q * 3 + 0] = n0;
        g_knn[q * 3 + 1] = n1;
        g_knn[q * 3 + 2] = n2;
    }
}

// ---------------- K3: edge weights ----------------
__global__ void ew_kernel() {
    int i = blockIdx.x * 8 + threadIdx.y;
    int lane = threadIdx.x;
    float xi0 = g_x[(size_t)i * DD + lane];
    float xi1 = g_x[(size_t)i * DD + lane + 32];
    float ni = g_xnorm[i];

    float deg = 1.0f;
    float ews[KK];
    #pragma unroll
    for (int k = 0; k < KK; k++) {
        int nb = g_knn[i * 3 + k];
        float dot = wsum(xi0 * g_x[(size_t)nb * DD + lane] +
                         xi1 * g_x[(size_t)nb * DD + lane + 32]);
        float z = dot / (g_xnorm[nb] * ni);
        float e = 1.0f / (1.0f + expf(-z));
        ews[k] = e;
        deg += e;
    }
    float dis = rsqrtf(deg);
    if (lane == 0) {
        #pragma unroll
        for (int k = 0; k < KK; k++) g_ew[i * 3 + k] = ews[k];
        g_dis[i] = dis;
    }
}

// ---------------- K4/K5: fused GCN (32 rows/block, col-pair per thread) ----------------
template <int EPI>
__global__ void gcn_kernel(const float* __restrict__ W, const float* __restrict__ b,
                           const float* __restrict__ lng, const float* __restrict__ lnb,
                           float* __restrict__ out) {
    __shared__ float sW[DD * DD];
    __shared__ float sZ[8][DD];
    int tid = threadIdx.y * 32 + threadIdx.x;
    for (int k = tid; k < DD * DD; k += 256) sW[k] = W[k];
    __syncthreads();

    int lane = threadIdx.x;
    int ty = threadIdx.y;
    int c0 = 2 * lane;
    const float* xin = (EPI == 1) ? g_x : g_t;
    float2 bb = *(const float2*)&b[c0];

    #pragma unroll
    for (int rb = 0; rb < 4; rb++) {
        int i = blockIdx.x * 32 + rb * 8 + ty;

        float dii = g_dis[i];
        float cs = dii * dii;
        float2 xi = *(const float2*)&xin[(size_t)i * DD + c0];
        float z0 = cs * xi.x, z1 = cs * xi.y;
        #pragma unroll
        for (int k = 0; k < KK; k++) {
            int nb = g_knn[i * 3 + k];
            float c = g_dis[nb] * g_ew[i * 3 + k] * dii;
            float2 xn = *(const float2*)&xin[(size_t)nb * DD + c0];
            z0 = fmaf(c, xn.x, z0);
            z1 = fmaf(c, xn.y, z1);
        }
        sZ[ty][c0] = z0;
        sZ[ty][c0 + 1] = z1;
        __syncwarp();

        float acc0 = 0.0f, acc1 = 0.0f;
        #pragma unroll
        for (int k = 0; k < DD; k++) {
            float zk = sZ[ty][k];
            float2 w = *(const float2*)&sW[k * DD + c0];
            acc0 = fmaf(zk, w.x, acc0);
            acc1 = fmaf(zk, w.y, acc1);
        }
        acc0 += bb.x;
        acc1 += bb.y;

        if (EPI == 1) {
            float m = wsum(acc0 + acc1) * (1.0f / 64.0f);
            float e0 = acc0 - m, e1 = acc1 - m;
            float v = wsum(e0 * e0 + e1 * e1) * (1.0f / 64.0f);
            float inv = rsqrtf(v + 1e-5f);
            float2 o;
            o.x = fmaxf(e0 * inv * lng[c0] + lnb[c0], 0.0f);
            o.y = fmaxf(e1 * inv * lng[c0 + 1] + lnb[c0 + 1], 0.0f);
            *(float2*)&g_t[(size_t)i * DD + c0] = o;
        } else {
            float2 xv = *(const float2*)&g_x[(size_t)i * DD + c0];
            float2 o;
            o.x = fmaf(2.0f, xv.x, acc0);
            o.y = fmaf(2.0f, xv.y, acc1);
            *(float2*)&out[(size_t)i * DD + c0] = o;
        }
        __syncwarp();
    }
}

// ---------------- launch ----------------
extern "C" void kernel_launch(void* const* d_in, const int* in_sizes, int n_in,
                              void* d_out, int out_size) {
    const float* feat   = (const float*)d_in[0];
    const float* coords = (const float*)d_in[4];
    const float* n1g = (const float*)d_in[5];
    const float* n1b = (const float*)d_in[6];
    const float* n2g = (const float*)d_in[7];
    const float* n2b = (const float*)d_in[8];
    const float* gng = (const float*)d_in[9];
    const float* gnb = (const float*)d_in[10];
    const float* W1  = (const float*)d_in[11];
    const float* b1  = (const float*)d_in[12];
    const float* W2  = (const float*)d_in[13];
    const float* b2  = (const float*)d_in[14];
    float* out = (float*)d_out;

    dim3 th(32, 8);
    grid_zero<<<CELLS / 256, 256>>>();
    build_ln<<<NN / 256 + NN / 8, 256>>>(coords, feat, n1g, n1b, n2g, n2b);
    knn_grid<<<NN * 8 / 256, 256>>>(coords);
    ew_kernel<<<NN / 8, th>>>();
    gcn_kernel<1><<<NN / 32, th>>>(W1, b1, gng, gnb, nullptr);
    gcn_kernel<2><<<NN / 32, th>>>(W2, b2, nullptr, nullptr, out);
}